// round 8
// baseline (speedup 1.0000x reference)
#include <cuda_runtime.h>
#include <cuda_bf16.h>
#include <cstdint>

// Fixed shapes from reference setup_inputs
#define BQ   32             // batch
#define NB   300            // boxes per batch
#define HH   1024
#define WW   1024
#define RPC  64             // rows per CTA
#define CHUNKS (HH / RPC)   // 16 row-chunks per image
#define NTH  256            // threads per CTA (8 warps)
#define NBOX_TOTAL (BQ * NB)   // 9600

// ---------------- device scratch (no allocations allowed) ----------------
__device__ float g_part[(size_t)BQ * CHUNKS * NB];   // per (batch, chunk, box) partials: 600 KB
__device__ float g_bsum[BQ];                         // per-batch sums
__device__ unsigned g_ctr;                           // combine completion ticket (self-resetting)

// Box edge computation — matches reference: clip(trunc(v).astype(int32), 0, dim-1)
__device__ __forceinline__ int4 make_box(float4 bx, float c) {
    float cx = bx.x, cy = bx.y, w = bx.z, h = bx.w;
    int x1 = min(max((int)truncf((cx - 0.5f * w) * (float)WW), 0), WW - 1);
    int x2 = min(max((int)truncf((cx + 0.5f * w) * (float)WW), 0), WW - 1);
    int y1 = min(max((int)truncf((cy - 0.5f * h) * (float)HH), 0), HH - 1);
    int y2 = min(max((int)truncf((cy + 0.5f * h) * (float)HH), 0), HH - 1);
    bool valid = (c >= 0.3f) && (x2 > x1) && (y2 > y1);
    if (!valid) { y1 = 0; y2 = 0; }   // empty y-range: accumulates nothing
    return make_int4(x1, y1, x2, y2);
}

// Sum of wtot[w] for w in [s1, s2) given the 8 per-warp totals (branchless).
__device__ __forceinline__ float segsum(float4 lo, float4 hi, int s1, int s2) {
    float s = 0.0f;
    s += (s1 <= 0 && 0 < s2) ? lo.x : 0.0f;
    s += (s1 <= 1 && 1 < s2) ? lo.y : 0.0f;
    s += (s1 <= 2 && 2 < s2) ? lo.z : 0.0f;
    s += (s1 <= 3 && 3 < s2) ? lo.w : 0.0f;
    s += (s1 <= 4 && 4 < s2) ? hi.x : 0.0f;
    s += (s1 <= 5 && 5 < s2) ? hi.y : 0.0f;
    s += (s1 <= 6 && 6 < s2) ? hi.z : 0.0f;
    s += (s1 <= 7 && 7 < s2) ? hi.w : 0.0f;
    return s;
}

// ---------------- phase 1: fused prep + row-scan + box rectangle sums ----------------
// grid: (CHUNKS, BQ) = 512 CTAs, 4 CTAs/SM -> single wave. 2 rows/iteration,
// ONE barrier per iteration: warps publish segment-LOCAL prefixes + per-warp
// totals; the cross-segment base is folded into the box lookup (segsum).
// Parity double-buffering makes the ps WAR hazard span two barriers.
__global__ void __launch_bounds__(NTH, 4)
rows_kernel(const float* __restrict__ seg,
            const float* __restrict__ boxes,
            const float* __restrict__ conf) {
    __shared__ float ps[2][2][WW];        // [parity][row01][col] segment-local exclusive prefix
    __shared__ float wtot[2][2][8];       // [parity][row01][warp] per-warp totals
    __shared__ int4  sbox[NB];            // this batch's boxes

    const int b     = blockIdx.y;
    const int chunk = blockIdx.x;
    const int t     = threadIdx.x;
    const int warp  = t >> 5;
    const int lane  = t & 31;

    // ---- inline prep: build the box table for this batch (redundant per CTA, trivial) ----
    for (int i = t; i < NB; i += NTH) {
        float4 bx = reinterpret_cast<const float4*>(boxes)[b * NB + i];
        sbox[i] = make_box(bx, conf[b * NB + i]);
    }
    __syncthreads();

    // Box ownership: thread t owns box t, plus t+256 when it exists (NB=300).
    const int4 B0 = sbox[t];
    const bool has1 = (t + NTH) < NB;
    const int4 B1 = has1 ? sbox[t + NTH] : make_int4(0, 0, 0, 0);
    const int s0a = B0.x >> 7, s0b = B0.z >> 7;   // segment indices of box 0 edges
    const int s1a = B1.x >> 7, s1b = B1.z >> 7;

    const size_t HW = (size_t)HH * WW;
    const float4* f1 = reinterpret_cast<const float4*>(
        seg + ((size_t)b * 3 + 1) * HW + (size_t)(chunk * RPC) * WW);  // driveway
    const float4* f2 = reinterpret_cast<const float4*>(
        seg + ((size_t)b * 3 + 2) * HW + (size_t)(chunk * RPC) * WW);  // footpath
    const int RSTRIDE = WW / 4;   // 256 float4 per row

    float acc0 = 0.0f, acc1 = 0.0f;

    // prefetch rows 0,1 for both classes
    float4 n1a = f1[t], n1b = f1[RSTRIDE + t];
    float4 n2a = f2[t], n2b = f2[RSTRIDE + t];

    #pragma unroll 1
    for (int r = 0; r < RPC; r += 2) {
        const int par = (r >> 1) & 1;
        float4 v1a = n1a, v1b = n1b, v2a = n2a, v2b = n2b;
        if (r + 2 < RPC) {   // prefetch next pair while scanning this one
            n1a = f1[(r + 2) * RSTRIDE + t];
            n1b = f1[(r + 3) * RSTRIDE + t];
            n2a = f2[(r + 2) * RSTRIDE + t];
            n2b = f2[(r + 3) * RSTRIDE + t];
        }

        // diff = footpath - driveway; thread-local inclusive prefix over 4 elems (x2 rows)
        float a0 = v2a.x - v1a.x, a1 = v2a.y - v1a.y, a2 = v2a.z - v1a.z, a3 = v2a.w - v1a.w;
        float b0 = v2b.x - v1b.x, b1 = v2b.y - v1b.y, b2 = v2b.z - v1b.z, b3 = v2b.w - v1b.w;
        float sA0 = a0, sA1 = sA0 + a1, sA2 = sA1 + a2, sA3 = sA2 + a3;
        float sB0 = b0, sB1 = sB0 + b1, sB2 = sB1 + b2, sB3 = sB2 + b3;
        float totA = sA3, totB = sB3;

        // two interleaved warp inclusive scans (segment-local, no cross-warp base)
        float incA = totA, incB = totB;
        #pragma unroll
        for (int o = 1; o < 32; o <<= 1) {
            float nA = __shfl_up_sync(0xFFFFFFFFu, incA, o);
            float nB = __shfl_up_sync(0xFFFFFFFFu, incB, o);
            if (lane >= o) { incA += nA; incB += nB; }
        }
        float exA = incA - totA, exB = incB - totB;   // exclusive within segment
        if (lane == 31) { wtot[par][0][warp] = incA; wtot[par][1][warp] = incB; }

        // segment-local exclusive prefix publication (one STS.128 per row)
        const int x4 = t << 2;
        *reinterpret_cast<float4*>(&ps[par][0][x4]) =
            make_float4(exA, exA + sA0, exA + sA1, exA + sA2);
        *reinterpret_cast<float4*>(&ps[par][1][x4]) =
            make_float4(exB, exB + sB0, exB + sB1, exB + sB2);
        __syncthreads();   // single barrier: publishes ps+wtot, fences WAR 2 iters back

        // box accumulation: sum over [x1,x2) = local(x2)-local(x1) + sum of full segments between
        const int y0 = chunk * RPC + r;
        const int y1r = y0 + 1;
        const float4 wA0 = *reinterpret_cast<const float4*>(&wtot[par][0][0]);
        const float4 wA1 = *reinterpret_cast<const float4*>(&wtot[par][0][4]);
        const float4 wB0 = *reinterpret_cast<const float4*>(&wtot[par][1][0]);
        const float4 wB1 = *reinterpret_cast<const float4*>(&wtot[par][1][4]);

        if (y0 >= B0.y && y0 < B0.w)
            acc0 += ps[par][0][B0.z] - ps[par][0][B0.x] + segsum(wA0, wA1, s0a, s0b);
        if (y1r >= B0.y && y1r < B0.w)
            acc0 += ps[par][1][B0.z] - ps[par][1][B0.x] + segsum(wB0, wB1, s0a, s0b);
        if (has1) {
            if (y0 >= B1.y && y0 < B1.w)
                acc1 += ps[par][0][B1.z] - ps[par][0][B1.x] + segsum(wA0, wA1, s1a, s1b);
            if (y1r >= B1.y && y1r < B1.w)
                acc1 += ps[par][1][B1.z] - ps[par][1][B1.x] + segsum(wB0, wB1, s1a, s1b);
        }
    }

    float* outp = g_part + ((size_t)b * CHUNKS + chunk) * NB;
    outp[t] = acc0;
    if (has1) outp[t + NTH] = acc1;
}

// ---------------- phase 2: per-batch combine + fused final (last CTA) ----------------
// CTA b reduces its batch's 300 boxes x 16 chunk-partials (19 KB, L2-resident),
// then the last CTA to finish reduces the 32 batch sums (fixed order ->
// deterministic) and resets the ticket counter for graph replay.
__global__ void __launch_bounds__(NTH)
combine_kernel(const float* __restrict__ boxes,
               const float* __restrict__ conf,
               float* __restrict__ out) {
    const int b = blockIdx.x;
    float v = 0.0f;
    for (int n = threadIdx.x; n < NB; n += NTH) {
        const int i = b * NB + n;
        // recompute scale = valid ? conf/area : 0
        float4 bx = reinterpret_cast<const float4*>(boxes)[i];
        float c = conf[i];
        float cx = bx.x, cy = bx.y, w = bx.z, h = bx.w;
        int x1 = min(max((int)truncf((cx - 0.5f * w) * (float)WW), 0), WW - 1);
        int x2 = min(max((int)truncf((cx + 0.5f * w) * (float)WW), 0), WW - 1);
        int y1 = min(max((int)truncf((cy - 0.5f * h) * (float)HH), 0), HH - 1);
        int y2 = min(max((int)truncf((cy + 0.5f * h) * (float)HH), 0), HH - 1);
        bool valid = (c >= 0.3f) && (x2 > x1) && (y2 > y1);
        float area = (float)((y2 - y1) * (x2 - x1));
        float scl = valid ? (c / area) : 0.0f;

        const float* p = g_part + (size_t)b * CHUNKS * NB + n;
        float r0 = 0.f, r1 = 0.f, r2 = 0.f, r3 = 0.f;
        #pragma unroll
        for (int cc = 0; cc < CHUNKS; cc += 4) {
            r0 += p[(size_t)(cc + 0) * NB];
            r1 += p[(size_t)(cc + 1) * NB];
            r2 += p[(size_t)(cc + 2) * NB];
            r3 += p[(size_t)(cc + 3) * NB];
        }
        float S = (r0 + r1) + (r2 + r3);
        v += fmaxf(S, 0.0f) * scl;
    }
    // block reduction -> per-batch sum (fixed order, deterministic)
    __shared__ float sm[NTH / 32];
    __shared__ bool last;
    #pragma unroll
    for (int o = 16; o > 0; o >>= 1) v += __shfl_down_sync(0xFFFFFFFFu, v, o);
    if ((threadIdx.x & 31) == 0) sm[threadIdx.x >> 5] = v;
    __syncthreads();
    if (threadIdx.x < 32) {
        float w = (threadIdx.x < NTH / 32) ? sm[threadIdx.x] : 0.0f;
        #pragma unroll
        for (int o = 4; o > 0; o >>= 1) w += __shfl_down_sync(0xFFFFFFFFu, w, o);
        if (threadIdx.x == 0) {
            g_bsum[b] = w;
            __threadfence();                               // publish before ticket
            unsigned tk = atomicAdd(&g_ctr, 1u);
            last = (tk == BQ - 1);
        }
    }
    __syncthreads();
    // last CTA: final reduce of 32 batch sums (fixed shuffle order -> deterministic)
    if (last && threadIdx.x < 32) {
        float f = g_bsum[threadIdx.x];
        #pragma unroll
        for (int o = 16; o > 0; o >>= 1) f += __shfl_down_sync(0xFFFFFFFFu, f, o);
        if (threadIdx.x == 0) {
            out[0] = f * (1.0f / (float)NBOX_TOTAL);
            g_ctr = 0;                                     // reset for next graph replay
        }
    }
}

// ---------------- launch ----------------
extern "C" void kernel_launch(void* const* d_in, const int* in_sizes, int n_in,
                              void* d_out, int out_size) {
    const float* det_boxes = (const float*)d_in[0];   // (32,300,4)
    const float* det_conf  = (const float*)d_in[1];   // (32,300)
    const float* seg       = (const float*)d_in[2];   // (32,3,1024,1024)
    float* out = (float*)d_out;

    dim3 grid(CHUNKS, BQ);
    rows_kernel<<<grid, NTH>>>(seg, det_boxes, det_conf);
    combine_kernel<<<BQ, NTH>>>(det_boxes, det_conf, out);
}